// round 15
// baseline (speedup 1.0000x reference)
#include <cuda_runtime.h>
#include <cuda_fp16.h>
#include <cstdint>
#include <math.h>

#define B_N   16384
#define K_N   50
#define V_N   100000
#define BK_N  (B_N * K_N)          // 819200
#define NTILE (BK_N / 128)         // 6400 tiles of 128 pairs
#define VTILE (V_N / 16)           // 6250 vocab warp-tiles

typedef unsigned int u32;

// ---------------------------------------------------------------------------
// Device scratch (static — no cudaMalloc allowed)
// Slot layout (per 64-col row, 32 u32): slot s = l4*8 + nt holds columns
// nt*8 + l4*2 + {0,1} as fp16x2  (l4 = lane&3 of the owning quad).
// ---------------------------------------------------------------------------
__device__ u32   g_P16  [(size_t)V_N * 32];    // 12.8MB fp16 table
__device__ u32   g_A1B16[(size_t)V_N * 32];    // 12.8MB fp16 table
__device__ u32   g_O16  [(size_t)BK_N * 32];   // 105MB o_history
__device__ float g_S    [(size_t)BK_N];        // attention scores
// fp16 B fragments: blocks of 2048 u32, layout [kt:4][nt:8][lane:32][reg:2]
// L: 0=w2W  1=a1W[0:64]  2=a2W  3=w1W[0:64]  4=a1W[64:128]
// L=5: W1X = [w1W[64:72]; w1b; 0...] K=16 — only kt=0 (512 u32) used
__device__ u32   g_Wf [6 * 2048];              // 48KB

// ---------------------------------------------------------------------------
// fp16 helpers
// ---------------------------------------------------------------------------
__device__ __forceinline__ u32 pack_h2(float v0, float v1) {
    __half2 h = __floats2half2_rn(v0, v1);
    return *reinterpret_cast<u32*>(&h);
}
__device__ __forceinline__ float2 h2f(u32 v) {
    return __half22float2(*reinterpret_cast<const __half2*>(&v));
}
// m16n8k16 row.col fp16 MMA, fp32 accumulate (sm_80+ baseline)
__device__ __forceinline__ void mma16816(float& d0, float& d1, float& d2, float& d3,
                                         u32 a0, u32 a1, u32 a2, u32 a3,
                                         u32 b0, u32 b1) {
    asm("mma.sync.aligned.m16n8k16.row.col.f32.f16.f16.f32 "
        "{%0,%1,%2,%3}, {%4,%5,%6,%7}, {%8,%9}, {%0,%1,%2,%3};"
        : "+f"(d0), "+f"(d1), "+f"(d2), "+f"(d3)
        : "r"(a0), "r"(a1), "r"(a2), "r"(a3), "r"(b0), "r"(b1));
}

// ---------------------------------------------------------------------------
// Kernel 0: fp16 B-fragments. 5 full matrices + W1X (labels+bias, kt0 only).
// ---------------------------------------------------------------------------
__global__ void __launch_bounds__(256) k_wfrag(const float* __restrict__ w2W,
                                               const float* __restrict__ a1W,
                                               const float* __restrict__ a2W,
                                               const float* __restrict__ w1W,
                                               const float* __restrict__ w1b)
{
    const int idx = blockIdx.x * 256 + threadIdx.x;   // 5120 + 256 = 5376
    if (idx >= 5376) return;

    if (idx >= 5120) {
        const int e    = idx - 5120;      // 0..255
        const int lane = e & 31;
        const int nt   = e >> 5;          // 0..7
        const int n  = nt * 8 + (lane >> 2);
        const int k0 = (lane & 3) * 2;    // 0,2,4,6
        const float w00 = w1W[(64 + k0    ) * 64 + n];
        const float w01 = w1W[(64 + k0 + 1) * 64 + n];
        const float w10 = (k0 == 0) ? w1b[n] : 0.f;
        const int f = 5 * 2048 + (nt * 32 + lane) * 2;
        g_Wf[f]     = pack_h2(w00, w01);
        g_Wf[f + 1] = pack_h2(w10, 0.f);
        return;
    }

    const int lane = idx & 31;
    const int nt   = (idx >> 5) & 7;
    const int kt   = (idx >> 8) & 3;
    const int L    = idx >> 10;

    const float* W;
    if (L == 0)      W = w2W;
    else if (L == 1) W = a1W;
    else if (L == 2) W = a2W;
    else if (L == 3) W = w1W;
    else             W = a1W + 4096;    // rows 64..127

    const int n  = nt * 8 + (lane >> 2);
    const int k0 = kt * 16 + (lane & 3) * 2;

    const int f = L * 2048 + ((kt*8 + nt)*32 + lane)*2;
    g_Wf[f]     = pack_h2(W[k0*64+n],     W[(k0+1)*64+n]);
    g_Wf[f + 1] = pack_h2(W[(k0+8)*64+n], W[(k0+9)*64+n]);
}

// ---------------------------------------------------------------------------
// Single-tile 64->64 GEMM (M=16), single-term A — k_pre.
// ---------------------------------------------------------------------------
__device__ __forceinline__ void gemm64_1t(float* D, const u32* ah,
                                          const u32* sBFL, int lane)
{
    #pragma unroll
    for (int nt = 0; nt < 8; nt++) {
        float d0=0.f,d1=0.f,d2=0.f,d3=0.f;
        #pragma unroll
        for (int kt = 0; kt < 4; kt++) {
            const uint2 b = *reinterpret_cast<const uint2*>(sBFL + (kt*8 + nt)*64 + lane*2);
            mma16816(d0,d1,d2,d3, ah[kt*4],ah[kt*4+1],ah[kt*4+2],ah[kt*4+3], b.x,b.y);
        }
        D[nt*4+0]=d0; D[nt*4+1]=d1; D[nt*4+2]=d2; D[nt*4+3]=d3;
    }
}

// Dual-tile (M=32), single-term A: k_main layers 2-4.
__device__ __forceinline__ void gemm64x2_1t(float* D,
                                            const u32* ahA, const u32* ahB,
                                            const u32* sBFL, int lane)
{
    #pragma unroll
    for (int nt = 0; nt < 8; nt++) {
        float d0=0.f,d1=0.f,d2=0.f,d3=0.f,d4=0.f,d5=0.f,d6=0.f,d7=0.f;
        #pragma unroll
        for (int kt = 0; kt < 4; kt++) {
            const uint2 b = *reinterpret_cast<const uint2*>(sBFL + (kt*8 + nt)*64 + lane*2);
            mma16816(d0,d1,d2,d3, ahA[kt*4],ahA[kt*4+1],ahA[kt*4+2],ahA[kt*4+3], b.x,b.y);
            mma16816(d4,d5,d6,d7, ahB[kt*4],ahB[kt*4+1],ahB[kt*4+2],ahB[kt*4+3], b.x,b.y);
        }
        D[nt*8+0]=d0; D[nt*8+1]=d1; D[nt*8+2]=d2; D[nt*8+3]=d3;
        D[nt*8+4]=d4; D[nt*8+5]=d5; D[nt*8+6]=d6; D[nt*8+7]=d7;
    }
}

// ---------------------------------------------------------------------------
// Kernel 1: HMMA per-vocab precompute of P16 and A1B16 (1-term fp16).
// ---------------------------------------------------------------------------
__global__ void __launch_bounds__(256) k_pre(const float* __restrict__ u2e)
{
    __shared__ u32 sBF[4096];

    const int tid = threadIdx.x;
    {
        const uint4* src = reinterpret_cast<const uint4*>(g_Wf + 3 * 2048);
        uint4* dst = reinterpret_cast<uint4*>(sBF);
        for (int i = tid; i < 1024; i += 256) dst[i] = src[i];
    }
    __syncthreads();

    const int wid  = tid >> 5;
    const int lane = tid & 31;
    const int g    = lane >> 2;
    const int q2   = (lane & 3) << 1;
    const int slot = (lane & 3) * 8;

    const int wt = blockIdx.x * 8 + wid;
    if (wt >= VTILE) return;
    const int v0 = wt * 16 + g;
    const int v1 = v0 + 8;

    u32 ah[16];
    #pragma unroll
    for (int rr = 0; rr < 2; rr++) {
        const float* Mr = u2e + (size_t)(wt*16 + g + rr*8) * 64;
        #pragma unroll
        for (int kt = 0; kt < 4; kt++) {
            const int c0 = kt*16 + q2;
            const float2 pa = *reinterpret_cast<const float2*>(Mr + c0);
            const float2 pb = *reinterpret_cast<const float2*>(Mr + c0 + 8);
            ah[kt*4 + rr]     = pack_h2(pa.x, pa.y);
            ah[kt*4 + 2 + rr] = pack_h2(pb.x, pb.y);
        }
    }

    float D[32];
    u32 p01[8], p23[8];

    gemm64_1t(D, ah, sBF, lane);
    #pragma unroll
    for (int nt = 0; nt < 8; nt++) {
        p01[nt] = pack_h2(D[nt*4+0], D[nt*4+1]);
        p23[nt] = pack_h2(D[nt*4+2], D[nt*4+3]);
    }
    {
        uint4* r0 = reinterpret_cast<uint4*>(&g_P16[(size_t)v0 * 32 + slot]);
        uint4* r1 = reinterpret_cast<uint4*>(&g_P16[(size_t)v1 * 32 + slot]);
        r0[0] = make_uint4(p01[0], p01[1], p01[2], p01[3]);
        r0[1] = make_uint4(p01[4], p01[5], p01[6], p01[7]);
        r1[0] = make_uint4(p23[0], p23[1], p23[2], p23[3]);
        r1[1] = make_uint4(p23[4], p23[5], p23[6], p23[7]);
    }

    gemm64_1t(D, ah, sBF + 2048, lane);
    #pragma unroll
    for (int nt = 0; nt < 8; nt++) {
        p01[nt] = pack_h2(D[nt*4+0], D[nt*4+1]);
        p23[nt] = pack_h2(D[nt*4+2], D[nt*4+3]);
    }
    {
        uint4* r0 = reinterpret_cast<uint4*>(&g_A1B16[(size_t)v0 * 32 + slot]);
        uint4* r1 = reinterpret_cast<uint4*>(&g_A1B16[(size_t)v1 * 32 + slot]);
        r0[0] = make_uint4(p01[0], p01[1], p01[2], p01[3]);
        r0[1] = make_uint4(p01[4], p01[5], p01[6], p01[7]);
        r1[0] = make_uint4(p23[0], p23[1], p23[2], p23[3]);
        r1[1] = make_uint4(p23[4], p23[5], p23[6], p23[7]);
    }
}

// ---------------------------------------------------------------------------
// Main kernel: layer 1 via MMA (labels+bias folded), layers 2-4 via MMA.
// fp16 slot-layout gathers for P and A1B. occ target 3 blocks/SM.
// ---------------------------------------------------------------------------
#define DSM_U32  (6144 + 512 + 4*64)   // 6912 u32 = 27648 B
#define DSM_BYTES (DSM_U32 * 4)

__global__ void __launch_bounds__(128, 3) k_main(
    const int*   __restrict__ nodes,
    const int*   __restrict__ nidx,
    const float* __restrict__ labels,
    const float* __restrict__ w2b,
    const float* __restrict__ a1b,
    const float* __restrict__ a2b,
    const float* __restrict__ a3W,
    const float* __restrict__ a3b)
{
    extern __shared__ u32 dsm[];
    u32*   sBF  = dsm;                       // 6144 u32: L=0,1,2
    u32*   sBF1 = dsm + 6144;                // 512 u32: W1X kt0
    float* sB2  = (float*)(dsm + 6656);      // 64
    float* sBa1 = sB2 + 64;
    float* sBa2 = sBa1 + 64;
    float* sA3  = sBa2 + 64;

    const int tid = threadIdx.x;
    {
        const uint4* src = reinterpret_cast<const uint4*>(g_Wf);
        uint4* dst = reinterpret_cast<uint4*>(sBF);
        for (int i = tid; i < 1536; i += 128) dst[i] = src[i];
        const uint4* src1 = reinterpret_cast<const uint4*>(g_Wf + 5 * 2048);
        uint4* dst1 = reinterpret_cast<uint4*>(sBF1);
        if (tid < 128) dst1[tid] = src1[tid];
        if (tid < 64) {
            sB2 [tid] = w2b[tid];
            sBa1[tid] = a1b[tid];
            sBa2[tid] = a2b[tid];
            sA3 [tid] = a3W[tid];
        }
    }
    __syncthreads();

    const float a3b0 = a3b[0];
    const int wid  = tid >> 5;             // 0..3
    const int lane = tid & 31;
    const int g    = lane >> 2;            // 0..7
    const int q2   = (lane & 3) << 1;      // 0,2,4,6
    const int l4x2 = (lane & 3) * 2;       // uint4 index within slot row
    const u32 onehot = (q2 == 0) ? pack_h2(1.f, 0.f) : 0u;

    for (int t = blockIdx.x; t < NTILE; t += gridDim.x) {
        const int pb = t * 128 + wid * 32 + g;   // rows pb, pb+8, pb+16, pb+24

        u32 ahA[16], ahB[16];
        float D[64];

        // ====== LAYER 1 via MMA: D = [labels,1,0..] @ [W1L; b1; 0] ======
        {
            u32 lF[8];
            const uint4* Pr[4];
            #pragma unroll
            for (int rr = 0; rr < 4; rr++) {
                const int p = pb + rr * 8;
                const float2 l2 = *reinterpret_cast<const float2*>(labels + (size_t)p * 8 + q2);
                u32* lf = (rr < 2) ? lF : lF + 4;
                const int sl = rr & 1;
                lf[0 + sl] = pack_h2(l2.x, l2.y);
                lf[2 + sl] = onehot;
                Pr[rr] = reinterpret_cast<const uint4*>(g_P16 + (size_t)__ldg(&nidx[p]) * 32);
            }

            #pragma unroll
            for (int nt = 0; nt < 8; nt++) {
                float d0=0.f,d1=0.f,d2=0.f,d3=0.f,d4=0.f,d5=0.f,d6=0.f,d7=0.f;
                const uint2 b = *reinterpret_cast<const uint2*>(sBF1 + nt*64 + lane*2);
                mma16816(d0,d1,d2,d3, lF[0],lF[1],lF[2],lF[3], b.x,b.y);
                mma16816(d4,d5,d6,d7, lF[4],lF[5],lF[6],lF[7], b.x,b.y);
                D[nt*8+0]=d0; D[nt*8+1]=d1; D[nt*8+2]=d2; D[nt*8+3]=d3;
                D[nt*8+4]=d4; D[nt*8+5]=d5; D[nt*8+6]=d6; D[nt*8+7]=d7;
            }

            // h = relu(D + P16[ni]) -> A fragments (hi only)
            #pragma unroll
            for (int rr = 0; rr < 4; rr++) {
                const uint4 pa = Pr[rr][l4x2];
                const uint4 pbq = Pr[rr][l4x2 + 1];
                u32* ah = (rr < 2) ? ahA : ahB;
                const int sl = rr & 1;
                const int hb = (rr >> 1) * 4 + sl * 2;
                const u32 pk[8] = { pa.x, pa.y, pa.z, pa.w, pbq.x, pbq.y, pbq.z, pbq.w };
                #pragma unroll
                for (int nt = 0; nt < 8; nt++) {
                    const float2 pv = h2f(pk[nt]);
                    const float v0 = fmaxf(D[nt*8 + hb + 0] + pv.x, 0.f);
                    const float v1 = fmaxf(D[nt*8 + hb + 1] + pv.y, 0.f);
                    ah[(nt >> 1)*4 + (nt & 1)*2 + sl] = pack_h2(v0, v1);
                }
            }
        }

        // ================= LAYER 2: o = relu(h @ W2 + b2) =================
        gemm64x2_1t(D, ahA, ahB, sBF, lane);
        {
            u32 p01[8], p23[8], q01[8], q23[8];
            #pragma unroll
            for (int nt = 0; nt < 8; nt++) {
                const int c0 = nt * 8 + q2;
                const int kt = nt >> 1, hf = nt & 1;
                const float b0 = sB2[c0], b1 = sB2[c0 + 1];
                p01[nt] = pack_h2(fmaxf(D[nt*8+0] + b0, 0.f), fmaxf(D[nt*8+1] + b1, 0.f));
                p23[nt] = pack_h2(fmaxf(D[nt*8+2] + b0, 0.f), fmaxf(D[nt*8+3] + b1, 0.f));
                q01[nt] = pack_h2(fmaxf(D[nt*8+4] + b0, 0.f), fmaxf(D[nt*8+5] + b1, 0.f));
                q23[nt] = pack_h2(fmaxf(D[nt*8+6] + b0, 0.f), fmaxf(D[nt*8+7] + b1, 0.f));
                ahA[kt*4 + hf*2 + 0] = p01[nt];
                ahA[kt*4 + hf*2 + 1] = p23[nt];
                ahB[kt*4 + hf*2 + 0] = q01[nt];
                ahB[kt*4 + hf*2 + 1] = q23[nt];
            }
            const int slot = (lane & 3) * 8;
            uint4* r0 = reinterpret_cast<uint4*>(&g_O16[(size_t)(pb     ) * 32 + slot]);
            uint4* r1 = reinterpret_cast<uint4*>(&g_O16[(size_t)(pb +  8) * 32 + slot]);
            uint4* r2 = reinterpret_cast<uint4*>(&g_O16[(size_t)(pb + 16) * 32 + slot]);
            uint4* r3 = reinterpret_cast<uint4*>(&g_O16[(size_t)(pb + 24) * 32 + slot]);
            r0[0] = make_uint4(p01[0], p01[1], p01[2], p01[3]);
            r0[1] = make_uint4(p01[4], p01[5], p01[6], p01[7]);
            r1[0] = make_uint4(p23[0], p23[1], p23[2], p23[3]);
            r1[1] = make_uint4(p23[4], p23[5], p23[6], p23[7]);
            r2[0] = make_uint4(q01[0], q01[1], q01[2], q01[3]);
            r2[1] = make_uint4(q01[4], q01[5], q01[6], q01[7]);
            r3[0] = make_uint4(q23[0], q23[1], q23[2], q23[3]);
            r3[1] = make_uint4(q23[4], q23[5], q23[6], q23[7]);
        }

        // ===== LAYER 3: a = relu(o @ A1a + A1B[node] + b) (scores only) ===
        const uint4* G[4];
        #pragma unroll
        for (int rr = 0; rr < 4; rr++)
            G[rr] = reinterpret_cast<const uint4*>(
                g_A1B16 + (size_t)__ldg(&nodes[(pb + rr * 8) / K_N]) * 32);

        gemm64x2_1t(D, ahA, ahB, sBF + 2048, lane);
        #pragma unroll
        for (int rr = 0; rr < 4; rr++) {
            const uint4 ga = G[rr][l4x2];
            const uint4 gb = G[rr][l4x2 + 1];
            u32* ah = (rr < 2) ? ahA : ahB;
            const int sl = rr & 1;
            const int hb = (rr >> 1) * 4 + sl * 2;
            const u32 gk[8] = { ga.x, ga.y, ga.z, ga.w, gb.x, gb.y, gb.z, gb.w };
            #pragma unroll
            for (int nt = 0; nt < 8; nt++) {
                const float2 gv = h2f(gk[nt]);
                const int c0 = nt * 8 + q2;
                const float v0 = fmaxf(D[nt*8 + hb + 0] + sBa1[c0]     + gv.x, 0.f);
                const float v1 = fmaxf(D[nt*8 + hb + 1] + sBa1[c0 + 1] + gv.y, 0.f);
                ah[(nt >> 1)*4 + (nt & 1)*2 + sl] = pack_h2(v0, v1);
            }
        }

        // ========= LAYER 4: a2 = relu(a @ A2 + b); score = a2 . a3 ========
        gemm64x2_1t(D, ahA, ahB, sBF + 4096, lane);
        float s[4] = {0.f, 0.f, 0.f, 0.f};
        #pragma unroll
        for (int nt = 0; nt < 8; nt++) {
            const int c0 = nt * 8 + q2;
            const float b0 = sBa2[c0], b1 = sBa2[c0 + 1];
            const float w0 = sA3[c0],  w1 = sA3[c0 + 1];
            #pragma unroll
            for (int half = 0; half < 2; half++) {
                const float v0 = fmaxf(D[nt*8 + half*4 + 0] + b0, 0.f);
                const float v1 = fmaxf(D[nt*8 + half*4 + 1] + b1, 0.f);
                const float v2 = fmaxf(D[nt*8 + half*4 + 2] + b0, 0.f);
                const float v3 = fmaxf(D[nt*8 + half*4 + 3] + b1, 0.f);
                s[half*2]     = fmaf(v0, w0, fmaf(v1, w1, s[half*2]));
                s[half*2 + 1] = fmaf(v2, w0, fmaf(v3, w1, s[half*2 + 1]));
            }
        }
        #pragma unroll
        for (int rr = 0; rr < 4; rr++) {
            float sv = s[rr];
            sv += __shfl_xor_sync(0xffffffffu, sv, 1);
            sv += __shfl_xor_sync(0xffffffffu, sv, 2);
            if ((lane & 3) == 0) g_S[pb + rr * 8] = sv + a3b0;
        }
    }
}

// ---------------------------------------------------------------------------
// Kernel 3: masked softmax + aggregate. Dual-row uint2 loads: lane covers
// row k + (lane>>4), slots 2*(lane&15), +1. Cross-half combine via shfl 16.
// ---------------------------------------------------------------------------
__global__ void __launch_bounds__(256) k_agg(const int*   __restrict__ nodes,
                                             const int*   __restrict__ nlen,
                                             const float* __restrict__ u2e,
                                             float*       __restrict__ out)
{
    const int wid  = (blockIdx.x * 256 + threadIdx.x) >> 5;
    const int lane = threadIdx.x & 31;
    if (wid >= B_N) return;
    const int b   = wid;
    const int len = nlen[b];

    if (len <= 0) {
        const int node = nodes[b];
        const float2* src = reinterpret_cast<const float2*>(u2e + (size_t)node * 64);
        reinterpret_cast<float2*>(out + (size_t)b * 64)[lane] = src[lane];
        return;
    }

    const float* Sb = g_S + (size_t)b * K_N;
    float s0 = (lane      < len) ? Sb[lane]      : -3.0e38f;
    float s1 = (lane + 32 < len) ? Sb[lane + 32] : -3.0e38f;

    float m = fmaxf(s0, s1);
    #pragma unroll
    for (int o = 16; o > 0; o >>= 1) m = fmaxf(m, __shfl_xor_sync(0xffffffffu, m, o));

    const float e0 = (lane      < len) ? expf(s0 - m) : 0.f;
    const float e1 = (lane + 32 < len) ? expf(s1 - m) : 0.f;

    float ss = e0 + e1;
    #pragma unroll
    for (int o = 16; o > 0; o >>= 1) ss += __shfl_xor_sync(0xffffffffu, ss, o);

    const float inv = 1.f / ss;
    const float w0 = e0 * inv;
    const float w1 = e1 * inv;

    const int half = lane >> 4;           // 0/1: which of the row pair
    const int sl2  = (lane & 15) * 2;     // slot pair base

    float2 aggA = make_float2(0.f, 0.f);
    float2 aggB = make_float2(0.f, 0.f);
    const u32* Ob = g_O16 + (size_t)b * K_N * 32;

    for (int k = 0; k < len; k += 2) {
        const int r = k + half;           // row this lane reads
        const float wa = __shfl_sync(0xffffffffu, w0, r & 31);
        const float wb = __shfl_sync(0xffffffffu, w1, r & 31);
        float ak = (r < 32) ? wa : wb;
        if (r >= len) ak = 0.f;
        const uint2 ov = *reinterpret_cast<const uint2*>(Ob + (size_t)r * 32 + sl2);
        const float2 oa = h2f(ov.x);
        const float2 ob = h2f(ov.y);
        aggA.x = fmaf(ak, oa.x, aggA.x);
        aggA.y = fmaf(ak, oa.y, aggA.y);
        aggB.x = fmaf(ak, ob.x, aggB.x);
        aggB.y = fmaf(ak, ob.y, aggB.y);
    }

    // combine halves (lane ^ 16 holds the other row's partial for same slots)
    aggA.x += __shfl_xor_sync(0xffffffffu, aggA.x, 16);
    aggA.y += __shfl_xor_sync(0xffffffffu, aggA.y, 16);
    aggB.x += __shfl_xor_sync(0xffffffffu, aggB.x, 16);
    aggB.y += __shfl_xor_sync(0xffffffffu, aggB.y, 16);

    if (lane < 16) {
        const int s0i = sl2;              // slot indices this lane owns
        const int s1i = sl2 + 1;
        const int c0 = (s0i & 7) * 8 + (s0i >> 3) * 2;
        const int c1 = (s1i & 7) * 8 + (s1i >> 3) * 2;
        *reinterpret_cast<float2*>(out + (size_t)b * 64 + c0) = aggA;
        *reinterpret_cast<float2*>(out + (size_t)b * 64 + c1) = aggB;
    }
}

// ---------------------------------------------------------------------------
// kernel_launch
// ---------------------------------------------------------------------------
extern "C" void kernel_launch(void* const* d_in, const int* in_sizes, int n_in,
                              void* d_out, int out_size)
{
    const int*   nodes  = (const int*)  d_in[0];
    const int*   nidx   = (const int*)  d_in[1];
    const int*   nlen   = (const int*)  d_in[2];
    const float* labels = (const float*)d_in[3];
    const float* u2e    = (const float*)d_in[4];
    const float* w1W    = (const float*)d_in[5];
    const float* w1b    = (const float*)d_in[6];
    const float* w2W    = (const float*)d_in[7];
    const float* w2b    = (const float*)d_in[8];
    const float* a1W    = (const float*)d_in[9];
    const float* a1b    = (const float*)d_in[10];
    const float* a2W    = (const float*)d_in[11];
    const float* a2b    = (const float*)d_in[12];
    const float* a3W    = (const float*)d_in[13];
    const float* a3b    = (const float*)d_in[14];
    float* out = (float*)d_out;

    cudaFuncSetAttribute(k_main, cudaFuncAttributeMaxDynamicSharedMemorySize, DSM_BYTES);

    k_wfrag<<<21, 256>>>(w2W, a1W, a2W, w1W, w1b);
    k_pre  <<<(VTILE + 7) / 8, 256>>>(u2e);
    k_main <<<296, 128, DSM_BYTES>>>(nodes, nidx, labels,
                                     w2b, a1b, a2b, a3W, a3b);
    k_agg  <<<(B_N * 32 + 255) / 256, 256>>>(nodes, nlen, u2e, out);
}

// round 16
// speedup vs baseline: 1.0743x; 1.0743x over previous
#include <cuda_runtime.h>
#include <cuda_fp16.h>
#include <cstdint>
#include <math.h>

#define B_N   16384
#define K_N   50
#define V_N   100000
#define BK_N  (B_N * K_N)          // 819200
#define NTILE (BK_N / 128)         // 6400 tiles of 128 pairs
#define VTILE (V_N / 16)           // 6250 vocab warp-tiles

typedef unsigned int u32;

// ---------------------------------------------------------------------------
// Device scratch (static — no cudaMalloc allowed)
// Slot layout (per 64-col row, 32 u32): slot s = l4*8 + nt holds columns
// nt*8 + l4*2 + {0,1} as fp16x2  (l4 = lane&3 of the owning quad).
// ---------------------------------------------------------------------------
__device__ u32   g_P16  [(size_t)V_N * 32];    // 12.8MB fp16 table
__device__ u32   g_A1B16[(size_t)V_N * 32];    // 12.8MB fp16 table
__device__ u32   g_O16  [(size_t)BK_N * 32];   // 105MB o_history
__device__ float g_S    [(size_t)BK_N];        // attention scores
// fp16 B fragments: blocks of 2048 u32, layout [kt:4][nt:8][lane:32][reg:2]
// L: 0=w2W  1=a1W[0:64]  2=a2W  3=w1W[0:64]  4=a1W[64:128]
// L=5: W1X = [w1W[64:72]; w1b; 0...] K=16 — only kt=0 (512 u32) used
__device__ u32   g_Wf [6 * 2048];              // 48KB

// ---------------------------------------------------------------------------
// fp16 helpers
// ---------------------------------------------------------------------------
__device__ __forceinline__ u32 pack_h2(float v0, float v1) {
    __half2 h = __floats2half2_rn(v0, v1);
    return *reinterpret_cast<u32*>(&h);
}
__device__ __forceinline__ float2 h2f(u32 v) {
    return __half22float2(*reinterpret_cast<const __half2*>(&v));
}
// m16n8k16 row.col fp16 MMA, fp32 accumulate (sm_80+ baseline)
__device__ __forceinline__ void mma16816(float& d0, float& d1, float& d2, float& d3,
                                         u32 a0, u32 a1, u32 a2, u32 a3,
                                         u32 b0, u32 b1) {
    asm("mma.sync.aligned.m16n8k16.row.col.f32.f16.f16.f32 "
        "{%0,%1,%2,%3}, {%4,%5,%6,%7}, {%8,%9}, {%0,%1,%2,%3};"
        : "+f"(d0), "+f"(d1), "+f"(d2), "+f"(d3)
        : "r"(a0), "r"(a1), "r"(a2), "r"(a3), "r"(b0), "r"(b1));
}

// ---------------------------------------------------------------------------
// Kernel 0: fp16 B-fragments. 5 full matrices + W1X (labels+bias, kt0 only).
// ---------------------------------------------------------------------------
__global__ void __launch_bounds__(256) k_wfrag(const float* __restrict__ w2W,
                                               const float* __restrict__ a1W,
                                               const float* __restrict__ a2W,
                                               const float* __restrict__ w1W,
                                               const float* __restrict__ w1b)
{
    const int idx = blockIdx.x * 256 + threadIdx.x;   // 5120 + 256 = 5376
    if (idx >= 5376) return;

    if (idx >= 5120) {
        const int e    = idx - 5120;      // 0..255
        const int lane = e & 31;
        const int nt   = e >> 5;          // 0..7
        const int n  = nt * 8 + (lane >> 2);
        const int k0 = (lane & 3) * 2;    // 0,2,4,6
        const float w00 = w1W[(64 + k0    ) * 64 + n];
        const float w01 = w1W[(64 + k0 + 1) * 64 + n];
        const float w10 = (k0 == 0) ? w1b[n] : 0.f;
        const int f = 5 * 2048 + (nt * 32 + lane) * 2;
        g_Wf[f]     = pack_h2(w00, w01);
        g_Wf[f + 1] = pack_h2(w10, 0.f);
        return;
    }

    const int lane = idx & 31;
    const int nt   = (idx >> 5) & 7;
    const int kt   = (idx >> 8) & 3;
    const int L    = idx >> 10;

    const float* W;
    if (L == 0)      W = w2W;
    else if (L == 1) W = a1W;
    else if (L == 2) W = a2W;
    else if (L == 3) W = w1W;
    else             W = a1W + 4096;    // rows 64..127

    const int n  = nt * 8 + (lane >> 2);
    const int k0 = kt * 16 + (lane & 3) * 2;

    const int f = L * 2048 + ((kt*8 + nt)*32 + lane)*2;
    g_Wf[f]     = pack_h2(W[k0*64+n],     W[(k0+1)*64+n]);
    g_Wf[f + 1] = pack_h2(W[(k0+8)*64+n], W[(k0+9)*64+n]);
}

// ---------------------------------------------------------------------------
// Single-tile 64->64 GEMM (M=16), single-term A — k_pre.
// ---------------------------------------------------------------------------
__device__ __forceinline__ void gemm64_1t(float* D, const u32* ah,
                                          const u32* sBFL, int lane)
{
    #pragma unroll
    for (int nt = 0; nt < 8; nt++) {
        float d0=0.f,d1=0.f,d2=0.f,d3=0.f;
        #pragma unroll
        for (int kt = 0; kt < 4; kt++) {
            const uint2 b = *reinterpret_cast<const uint2*>(sBFL + (kt*8 + nt)*64 + lane*2);
            mma16816(d0,d1,d2,d3, ah[kt*4],ah[kt*4+1],ah[kt*4+2],ah[kt*4+3], b.x,b.y);
        }
        D[nt*4+0]=d0; D[nt*4+1]=d1; D[nt*4+2]=d2; D[nt*4+3]=d3;
    }
}

// Dual-tile (M=32), single-term A: k_main layers 2-4.
__device__ __forceinline__ void gemm64x2_1t(float* D,
                                            const u32* ahA, const u32* ahB,
                                            const u32* sBFL, int lane)
{
    #pragma unroll
    for (int nt = 0; nt < 8; nt++) {
        float d0=0.f,d1=0.f,d2=0.f,d3=0.f,d4=0.f,d5=0.f,d6=0.f,d7=0.f;
        #pragma unroll
        for (int kt = 0; kt < 4; kt++) {
            const uint2 b = *reinterpret_cast<const uint2*>(sBFL + (kt*8 + nt)*64 + lane*2);
            mma16816(d0,d1,d2,d3, ahA[kt*4],ahA[kt*4+1],ahA[kt*4+2],ahA[kt*4+3], b.x,b.y);
            mma16816(d4,d5,d6,d7, ahB[kt*4],ahB[kt*4+1],ahB[kt*4+2],ahB[kt*4+3], b.x,b.y);
        }
        D[nt*8+0]=d0; D[nt*8+1]=d1; D[nt*8+2]=d2; D[nt*8+3]=d3;
        D[nt*8+4]=d4; D[nt*8+5]=d5; D[nt*8+6]=d6; D[nt*8+7]=d7;
    }
}

// ---------------------------------------------------------------------------
// Kernel 1: HMMA per-vocab precompute of P16 and A1B16 (1-term fp16).
// ---------------------------------------------------------------------------
__global__ void __launch_bounds__(256) k_pre(const float* __restrict__ u2e)
{
    __shared__ u32 sBF[4096];

    const int tid = threadIdx.x;
    {
        const uint4* src = reinterpret_cast<const uint4*>(g_Wf + 3 * 2048);
        uint4* dst = reinterpret_cast<uint4*>(sBF);
        for (int i = tid; i < 1024; i += 256) dst[i] = src[i];
    }
    __syncthreads();

    const int wid  = tid >> 5;
    const int lane = tid & 31;
    const int g    = lane >> 2;
    const int q2   = (lane & 3) << 1;
    const int slot = (lane & 3) * 8;

    const int wt = blockIdx.x * 8 + wid;
    if (wt >= VTILE) return;
    const int v0 = wt * 16 + g;
    const int v1 = v0 + 8;

    u32 ah[16];
    #pragma unroll
    for (int rr = 0; rr < 2; rr++) {
        const float* Mr = u2e + (size_t)(wt*16 + g + rr*8) * 64;
        #pragma unroll
        for (int kt = 0; kt < 4; kt++) {
            const int c0 = kt*16 + q2;
            const float2 pa = *reinterpret_cast<const float2*>(Mr + c0);
            const float2 pb = *reinterpret_cast<const float2*>(Mr + c0 + 8);
            ah[kt*4 + rr]     = pack_h2(pa.x, pa.y);
            ah[kt*4 + 2 + rr] = pack_h2(pb.x, pb.y);
        }
    }

    float D[32];
    u32 p01[8], p23[8];

    gemm64_1t(D, ah, sBF, lane);
    #pragma unroll
    for (int nt = 0; nt < 8; nt++) {
        p01[nt] = pack_h2(D[nt*4+0], D[nt*4+1]);
        p23[nt] = pack_h2(D[nt*4+2], D[nt*4+3]);
    }
    {
        uint4* r0 = reinterpret_cast<uint4*>(&g_P16[(size_t)v0 * 32 + slot]);
        uint4* r1 = reinterpret_cast<uint4*>(&g_P16[(size_t)v1 * 32 + slot]);
        r0[0] = make_uint4(p01[0], p01[1], p01[2], p01[3]);
        r0[1] = make_uint4(p01[4], p01[5], p01[6], p01[7]);
        r1[0] = make_uint4(p23[0], p23[1], p23[2], p23[3]);
        r1[1] = make_uint4(p23[4], p23[5], p23[6], p23[7]);
    }

    gemm64_1t(D, ah, sBF + 2048, lane);
    #pragma unroll
    for (int nt = 0; nt < 8; nt++) {
        p01[nt] = pack_h2(D[nt*4+0], D[nt*4+1]);
        p23[nt] = pack_h2(D[nt*4+2], D[nt*4+3]);
    }
    {
        uint4* r0 = reinterpret_cast<uint4*>(&g_A1B16[(size_t)v0 * 32 + slot]);
        uint4* r1 = reinterpret_cast<uint4*>(&g_A1B16[(size_t)v1 * 32 + slot]);
        r0[0] = make_uint4(p01[0], p01[1], p01[2], p01[3]);
        r0[1] = make_uint4(p01[4], p01[5], p01[6], p01[7]);
        r1[0] = make_uint4(p23[0], p23[1], p23[2], p23[3]);
        r1[1] = make_uint4(p23[4], p23[5], p23[6], p23[7]);
    }
}

// ---------------------------------------------------------------------------
// Main kernel: layer 1 via MMA (labels+bias folded), layers 2-4 via MMA.
// fp16 slot-layout gathers for P and A1B. occ 2 blocks/SM (R14 proven).
// ---------------------------------------------------------------------------
#define DSM_U32  (6144 + 512 + 4*64)   // 6912 u32 = 27648 B
#define DSM_BYTES (DSM_U32 * 4)

__global__ void __launch_bounds__(128, 2) k_main(
    const int*   __restrict__ nodes,
    const int*   __restrict__ nidx,
    const float* __restrict__ labels,
    const float* __restrict__ w2b,
    const float* __restrict__ a1b,
    const float* __restrict__ a2b,
    const float* __restrict__ a3W,
    const float* __restrict__ a3b)
{
    extern __shared__ u32 dsm[];
    u32*   sBF  = dsm;                       // 6144 u32: L=0,1,2
    u32*   sBF1 = dsm + 6144;                // 512 u32: W1X kt0
    float* sB2  = (float*)(dsm + 6656);      // 64
    float* sBa1 = sB2 + 64;
    float* sBa2 = sBa1 + 64;
    float* sA3  = sBa2 + 64;

    const int tid = threadIdx.x;
    {
        const uint4* src = reinterpret_cast<const uint4*>(g_Wf);
        uint4* dst = reinterpret_cast<uint4*>(sBF);
        for (int i = tid; i < 1536; i += 128) dst[i] = src[i];
        const uint4* src1 = reinterpret_cast<const uint4*>(g_Wf + 5 * 2048);
        uint4* dst1 = reinterpret_cast<uint4*>(sBF1);
        if (tid < 128) dst1[tid] = src1[tid];
        if (tid < 64) {
            sB2 [tid] = w2b[tid];
            sBa1[tid] = a1b[tid];
            sBa2[tid] = a2b[tid];
            sA3 [tid] = a3W[tid];
        }
    }
    __syncthreads();

    const float a3b0 = a3b[0];
    const int wid  = tid >> 5;             // 0..3
    const int lane = tid & 31;
    const int g    = lane >> 2;            // 0..7
    const int q2   = (lane & 3) << 1;      // 0,2,4,6
    const int l4x2 = (lane & 3) * 2;       // uint4 index within slot row
    const u32 onehot = (q2 == 0) ? pack_h2(1.f, 0.f) : 0u;

    for (int t = blockIdx.x; t < NTILE; t += gridDim.x) {
        const int pb = t * 128 + wid * 32 + g;   // rows pb, pb+8, pb+16, pb+24

        u32 ahA[16], ahB[16];
        float D[64];

        // ====== LAYER 1 via MMA: D = [labels,1,0..] @ [W1L; b1; 0] ======
        {
            u32 lF[8];
            const uint4* Pr[4];
            #pragma unroll
            for (int rr = 0; rr < 4; rr++) {
                const int p = pb + rr * 8;
                const float2 l2 = *reinterpret_cast<const float2*>(labels + (size_t)p * 8 + q2);
                u32* lf = (rr < 2) ? lF : lF + 4;
                const int sl = rr & 1;
                lf[0 + sl] = pack_h2(l2.x, l2.y);
                lf[2 + sl] = onehot;
                Pr[rr] = reinterpret_cast<const uint4*>(g_P16 + (size_t)__ldg(&nidx[p]) * 32);
            }

            #pragma unroll
            for (int nt = 0; nt < 8; nt++) {
                float d0=0.f,d1=0.f,d2=0.f,d3=0.f,d4=0.f,d5=0.f,d6=0.f,d7=0.f;
                const uint2 b = *reinterpret_cast<const uint2*>(sBF1 + nt*64 + lane*2);
                mma16816(d0,d1,d2,d3, lF[0],lF[1],lF[2],lF[3], b.x,b.y);
                mma16816(d4,d5,d6,d7, lF[4],lF[5],lF[6],lF[7], b.x,b.y);
                D[nt*8+0]=d0; D[nt*8+1]=d1; D[nt*8+2]=d2; D[nt*8+3]=d3;
                D[nt*8+4]=d4; D[nt*8+5]=d5; D[nt*8+6]=d6; D[nt*8+7]=d7;
            }

            // h = relu(D + P16[ni]) -> A fragments (hi only)
            #pragma unroll
            for (int rr = 0; rr < 4; rr++) {
                const uint4 pa = Pr[rr][l4x2];
                const uint4 pbq = Pr[rr][l4x2 + 1];
                u32* ah = (rr < 2) ? ahA : ahB;
                const int sl = rr & 1;
                const int hb = (rr >> 1) * 4 + sl * 2;
                const u32 pk[8] = { pa.x, pa.y, pa.z, pa.w, pbq.x, pbq.y, pbq.z, pbq.w };
                #pragma unroll
                for (int nt = 0; nt < 8; nt++) {
                    const float2 pv = h2f(pk[nt]);
                    const float v0 = fmaxf(D[nt*8 + hb + 0] + pv.x, 0.f);
                    const float v1 = fmaxf(D[nt*8 + hb + 1] + pv.y, 0.f);
                    ah[(nt >> 1)*4 + (nt & 1)*2 + sl] = pack_h2(v0, v1);
                }
            }
        }

        // ================= LAYER 2: o = relu(h @ W2 + b2) =================
        gemm64x2_1t(D, ahA, ahB, sBF, lane);
        {
            u32 p01[8], p23[8], q01[8], q23[8];
            #pragma unroll
            for (int nt = 0; nt < 8; nt++) {
                const int c0 = nt * 8 + q2;
                const int kt = nt >> 1, hf = nt & 1;
                const float b0 = sB2[c0], b1 = sB2[c0 + 1];
                p01[nt] = pack_h2(fmaxf(D[nt*8+0] + b0, 0.f), fmaxf(D[nt*8+1] + b1, 0.f));
                p23[nt] = pack_h2(fmaxf(D[nt*8+2] + b0, 0.f), fmaxf(D[nt*8+3] + b1, 0.f));
                q01[nt] = pack_h2(fmaxf(D[nt*8+4] + b0, 0.f), fmaxf(D[nt*8+5] + b1, 0.f));
                q23[nt] = pack_h2(fmaxf(D[nt*8+6] + b0, 0.f), fmaxf(D[nt*8+7] + b1, 0.f));
                ahA[kt*4 + hf*2 + 0] = p01[nt];
                ahA[kt*4 + hf*2 + 1] = p23[nt];
                ahB[kt*4 + hf*2 + 0] = q01[nt];
                ahB[kt*4 + hf*2 + 1] = q23[nt];
            }
            const int slot = (lane & 3) * 8;
            uint4* r0 = reinterpret_cast<uint4*>(&g_O16[(size_t)(pb     ) * 32 + slot]);
            uint4* r1 = reinterpret_cast<uint4*>(&g_O16[(size_t)(pb +  8) * 32 + slot]);
            uint4* r2 = reinterpret_cast<uint4*>(&g_O16[(size_t)(pb + 16) * 32 + slot]);
            uint4* r3 = reinterpret_cast<uint4*>(&g_O16[(size_t)(pb + 24) * 32 + slot]);
            r0[0] = make_uint4(p01[0], p01[1], p01[2], p01[3]);
            r0[1] = make_uint4(p01[4], p01[5], p01[6], p01[7]);
            r1[0] = make_uint4(p23[0], p23[1], p23[2], p23[3]);
            r1[1] = make_uint4(p23[4], p23[5], p23[6], p23[7]);
            r2[0] = make_uint4(q01[0], q01[1], q01[2], q01[3]);
            r2[1] = make_uint4(q01[4], q01[5], q01[6], q01[7]);
            r3[0] = make_uint4(q23[0], q23[1], q23[2], q23[3]);
            r3[1] = make_uint4(q23[4], q23[5], q23[6], q23[7]);
        }

        // ===== LAYER 3: a = relu(o @ A1a + A1B[node] + b) (scores only) ===
        const uint4* G[4];
        #pragma unroll
        for (int rr = 0; rr < 4; rr++)
            G[rr] = reinterpret_cast<const uint4*>(
                g_A1B16 + (size_t)__ldg(&nodes[(pb + rr * 8) / K_N]) * 32);

        gemm64x2_1t(D, ahA, ahB, sBF + 2048, lane);
        #pragma unroll
        for (int rr = 0; rr < 4; rr++) {
            const uint4 ga = G[rr][l4x2];
            const uint4 gb = G[rr][l4x2 + 1];
            u32* ah = (rr < 2) ? ahA : ahB;
            const int sl = rr & 1;
            const int hb = (rr >> 1) * 4 + sl * 2;
            const u32 gk[8] = { ga.x, ga.y, ga.z, ga.w, gb.x, gb.y, gb.z, gb.w };
            #pragma unroll
            for (int nt = 0; nt < 8; nt++) {
                const float2 gv = h2f(gk[nt]);
                const int c0 = nt * 8 + q2;
                const float v0 = fmaxf(D[nt*8 + hb + 0] + sBa1[c0]     + gv.x, 0.f);
                const float v1 = fmaxf(D[nt*8 + hb + 1] + sBa1[c0 + 1] + gv.y, 0.f);
                ah[(nt >> 1)*4 + (nt & 1)*2 + sl] = pack_h2(v0, v1);
            }
        }

        // ========= LAYER 4: a2 = relu(a @ A2 + b); score = a2 . a3 ========
        gemm64x2_1t(D, ahA, ahB, sBF + 4096, lane);
        float s[4] = {0.f, 0.f, 0.f, 0.f};
        #pragma unroll
        for (int nt = 0; nt < 8; nt++) {
            const int c0 = nt * 8 + q2;
            const float b0 = sBa2[c0], b1 = sBa2[c0 + 1];
            const float w0 = sA3[c0],  w1 = sA3[c0 + 1];
            #pragma unroll
            for (int half = 0; half < 2; half++) {
                const float v0 = fmaxf(D[nt*8 + half*4 + 0] + b0, 0.f);
                const float v1 = fmaxf(D[nt*8 + half*4 + 1] + b1, 0.f);
                const float v2 = fmaxf(D[nt*8 + half*4 + 2] + b0, 0.f);
                const float v3 = fmaxf(D[nt*8 + half*4 + 3] + b1, 0.f);
                s[half*2]     = fmaf(v0, w0, fmaf(v1, w1, s[half*2]));
                s[half*2 + 1] = fmaf(v2, w0, fmaf(v3, w1, s[half*2 + 1]));
            }
        }
        #pragma unroll
        for (int rr = 0; rr < 4; rr++) {
            float sv = s[rr];
            sv += __shfl_xor_sync(0xffffffffu, sv, 1);
            sv += __shfl_xor_sync(0xffffffffu, sv, 2);
            if ((lane & 3) == 0) g_S[pb + rr * 8] = sv + a3b0;
        }
    }
}

// ---------------------------------------------------------------------------
// Kernel 3: masked softmax + aggregate (R14 proven loop). Column map:
// slot=lane ↔ columns (lane&7)*8 + (lane>>3)*2 + {0,1}.
// ---------------------------------------------------------------------------
__global__ void __launch_bounds__(256) k_agg(const int*   __restrict__ nodes,
                                             const int*   __restrict__ nlen,
                                             const float* __restrict__ u2e,
                                             float*       __restrict__ out)
{
    const int wid  = (blockIdx.x * 256 + threadIdx.x) >> 5;
    const int lane = threadIdx.x & 31;
    if (wid >= B_N) return;
    const int b   = wid;
    const int len = nlen[b];

    if (len <= 0) {
        const int node = nodes[b];
        const float2* src = reinterpret_cast<const float2*>(u2e + (size_t)node * 64);
        reinterpret_cast<float2*>(out + (size_t)b * 64)[lane] = src[lane];
        return;
    }

    const float* Sb = g_S + (size_t)b * K_N;
    float s0 = (lane      < len) ? Sb[lane]      : -3.0e38f;
    float s1 = (lane + 32 < len) ? Sb[lane + 32] : -3.0e38f;

    float m = fmaxf(s0, s1);
    #pragma unroll
    for (int o = 16; o > 0; o >>= 1) m = fmaxf(m, __shfl_xor_sync(0xffffffffu, m, o));

    const float e0 = (lane      < len) ? expf(s0 - m) : 0.f;
    const float e1 = (lane + 32 < len) ? expf(s1 - m) : 0.f;

    float ss = e0 + e1;
    #pragma unroll
    for (int o = 16; o > 0; o >>= 1) ss += __shfl_xor_sync(0xffffffffu, ss, o);

    const float inv = 1.f / ss;
    const float w0 = e0 * inv;
    const float w1 = e1 * inv;

    float2 agg = make_float2(0.f, 0.f);
    const u32* Ob = g_O16 + (size_t)b * K_N * 32;
    for (int k = 0; k < len; k++) {
        const float ak = (k < 32) ? __shfl_sync(0xffffffffu, w0, k)
                                  : __shfl_sync(0xffffffffu, w1, k - 32);
        const u32 ov = Ob[k * 32 + lane];
        const float2 of = h2f(ov);
        agg.x = fmaf(ak, of.x, agg.x);
        agg.y = fmaf(ak, of.y, agg.y);
    }
    const int col = (lane & 7) * 8 + (lane >> 3) * 2;
    *reinterpret_cast<float2*>(out + (size_t)b * 64 + col) = agg;
}

// ---------------------------------------------------------------------------
// kernel_launch
// ---------------------------------------------------------------------------
extern "C" void kernel_launch(void* const* d_in, const int* in_sizes, int n_in,
                              void* d_out, int out_size)
{
    const int*   nodes  = (const int*)  d_in[0];
    const int*   nidx   = (const int*)  d_in[1];
    const int*   nlen   = (const int*)  d_in[2];
    const float* labels = (const float*)d_in[3];
    const float* u2e    = (const float*)d_in[4];
    const float* w1W    = (const float*)d_in[5];
    const float* w1b    = (const float*)d_in[6];
    const float* w2W    = (const float*)d_in[7];
    const float* w2b    = (const float*)d_in[8];
    const float* a1W    = (const float*)d_in[9];
    const float* a1b    = (const float*)d_in[10];
    const float* a2W    = (const float*)d_in[11];
    const float* a2b    = (const float*)d_in[12];
    const float* a3W    = (const float*)d_in[13];
    const float* a3b    = (const float*)d_in[14];
    float* out = (float*)d_out;

    cudaFuncSetAttribute(k_main, cudaFuncAttributeMaxDynamicSharedMemorySize, DSM_BYTES);

    k_wfrag<<<21, 256>>>(w2W, a1W, a2W, w1W, w1b);
    k_pre  <<<(VTILE + 7) / 8, 256>>>(u2e);
    k_main <<<296, 128, DSM_BYTES>>>(nodes, nidx, labels,
                                     w2b, a1b, a2b, a3W, a3b);
    k_agg  <<<(B_N * 32 + 255) / 256, 256>>>(nodes, nlen, u2e, out);
}

// round 17
// speedup vs baseline: 1.2009x; 1.1178x over previous
#include <cuda_runtime.h>
#include <cuda_fp16.h>
#include <cstdint>
#include <math.h>

#define B_N   16384
#define K_N   50
#define V_N   100000
#define BK_N  (B_N * K_N)          // 819200
#define NTILE (BK_N / 128)         // 6400 tiles of 128 pairs
#define VTILE (V_N / 16)           // 6250 vocab warp-tiles (P table)
#define BTILE (B_N / 16)           // 1024 node-slot warp-tiles (A1Bn table)
#define PBLK  ((VTILE + 7) / 8)    // 782 blocks for P
#define NBLK  ((BTILE + 7) / 8)    // 128 blocks for A1Bn

typedef unsigned int u32;

// ---------------------------------------------------------------------------
// Device scratch (static — no cudaMalloc allowed)
// Slot layout (per 64-col row, 32 u32): slot s = l4*8 + nt holds columns
// nt*8 + l4*2 + {0,1} as fp16x2  (l4 = lane&3 of the owning quad).
// ---------------------------------------------------------------------------
__device__ u32   g_P16   [(size_t)V_N * 32];   // 12.8MB fp16 table
__device__ u32   g_A1Bn16[(size_t)B_N * 32];   // 2MB per-node-slot table
__device__ u32   g_O16   [(size_t)BK_N * 32];  // 105MB o_history
__device__ float g_S     [(size_t)BK_N];       // attention scores
// fp16 B fragments: blocks of 2048 u32, layout [kt:4][nt:8][lane:32][reg:2]
// L: 0=w2W  1=a1W[0:64]  2=a2W  3=w1W[0:64]  4=a1W[64:128]
// L=5: W1X = [w1W[64:72]; w1b; 0...] K=16 — only kt=0 (512 u32) used
__device__ u32   g_Wf [6 * 2048];              // 48KB

// ---------------------------------------------------------------------------
// fp16 helpers
// ---------------------------------------------------------------------------
__device__ __forceinline__ u32 pack_h2(float v0, float v1) {
    __half2 h = __floats2half2_rn(v0, v1);
    return *reinterpret_cast<u32*>(&h);
}
__device__ __forceinline__ float2 h2f(u32 v) {
    return __half22float2(*reinterpret_cast<const __half2*>(&v));
}
// m16n8k16 row.col fp16 MMA, fp32 accumulate (sm_80+ baseline)
__device__ __forceinline__ void mma16816(float& d0, float& d1, float& d2, float& d3,
                                         u32 a0, u32 a1, u32 a2, u32 a3,
                                         u32 b0, u32 b1) {
    asm("mma.sync.aligned.m16n8k16.row.col.f32.f16.f16.f32 "
        "{%0,%1,%2,%3}, {%4,%5,%6,%7}, {%8,%9}, {%0,%1,%2,%3};"
        : "+f"(d0), "+f"(d1), "+f"(d2), "+f"(d3)
        : "r"(a0), "r"(a1), "r"(a2), "r"(a3), "r"(b0), "r"(b1));
}

// ---------------------------------------------------------------------------
// Kernel 0: fp16 B-fragments. 5 full matrices + W1X (labels+bias, kt0 only).
// ---------------------------------------------------------------------------
__global__ void __launch_bounds__(256) k_wfrag(const float* __restrict__ w2W,
                                               const float* __restrict__ a1W,
                                               const float* __restrict__ a2W,
                                               const float* __restrict__ w1W,
                                               const float* __restrict__ w1b)
{
    const int idx = blockIdx.x * 256 + threadIdx.x;   // 5120 + 256 = 5376
    if (idx >= 5376) return;

    if (idx >= 5120) {
        const int e    = idx - 5120;      // 0..255
        const int lane = e & 31;
        const int nt   = e >> 5;          // 0..7
        const int n  = nt * 8 + (lane >> 2);
        const int k0 = (lane & 3) * 2;    // 0,2,4,6
        const float w00 = w1W[(64 + k0    ) * 64 + n];
        const float w01 = w1W[(64 + k0 + 1) * 64 + n];
        const float w10 = (k0 == 0) ? w1b[n] : 0.f;
        const int f = 5 * 2048 + (nt * 32 + lane) * 2;
        g_Wf[f]     = pack_h2(w00, w01);
        g_Wf[f + 1] = pack_h2(w10, 0.f);
        return;
    }

    const int lane = idx & 31;
    const int nt   = (idx >> 5) & 7;
    const int kt   = (idx >> 8) & 3;
    const int L    = idx >> 10;

    const float* W;
    if (L == 0)      W = w2W;
    else if (L == 1) W = a1W;
    else if (L == 2) W = a2W;
    else if (L == 3) W = w1W;
    else             W = a1W + 4096;    // rows 64..127

    const int n  = nt * 8 + (lane >> 2);
    const int k0 = kt * 16 + (lane & 3) * 2;

    const int f = L * 2048 + ((kt*8 + nt)*32 + lane)*2;
    g_Wf[f]     = pack_h2(W[k0*64+n],     W[(k0+1)*64+n]);
    g_Wf[f + 1] = pack_h2(W[(k0+8)*64+n], W[(k0+9)*64+n]);
}

// ---------------------------------------------------------------------------
// Single-tile 64->64 GEMM (M=16), single-term A — k_pre.
// ---------------------------------------------------------------------------
__device__ __forceinline__ void gemm64_1t(float* D, const u32* ah,
                                          const u32* sBFL, int lane)
{
    #pragma unroll
    for (int nt = 0; nt < 8; nt++) {
        float d0=0.f,d1=0.f,d2=0.f,d3=0.f;
        #pragma unroll
        for (int kt = 0; kt < 4; kt++) {
            const uint2 b = *reinterpret_cast<const uint2*>(sBFL + (kt*8 + nt)*64 + lane*2);
            mma16816(d0,d1,d2,d3, ah[kt*4],ah[kt*4+1],ah[kt*4+2],ah[kt*4+3], b.x,b.y);
        }
        D[nt*4+0]=d0; D[nt*4+1]=d1; D[nt*4+2]=d2; D[nt*4+3]=d3;
    }
}

// Dual-tile (M=32), single-term A: k_main layers 2-4.
__device__ __forceinline__ void gemm64x2_1t(float* D,
                                            const u32* ahA, const u32* ahB,
                                            const u32* sBFL, int lane)
{
    #pragma unroll
    for (int nt = 0; nt < 8; nt++) {
        float d0=0.f,d1=0.f,d2=0.f,d3=0.f,d4=0.f,d5=0.f,d6=0.f,d7=0.f;
        #pragma unroll
        for (int kt = 0; kt < 4; kt++) {
            const uint2 b = *reinterpret_cast<const uint2*>(sBFL + (kt*8 + nt)*64 + lane*2);
            mma16816(d0,d1,d2,d3, ahA[kt*4],ahA[kt*4+1],ahA[kt*4+2],ahA[kt*4+3], b.x,b.y);
            mma16816(d4,d5,d6,d7, ahB[kt*4],ahB[kt*4+1],ahB[kt*4+2],ahB[kt*4+3], b.x,b.y);
        }
        D[nt*8+0]=d0; D[nt*8+1]=d1; D[nt*8+2]=d2; D[nt*8+3]=d3;
        D[nt*8+4]=d4; D[nt*8+5]=d5; D[nt*8+6]=d6; D[nt*8+7]=d7;
    }
}

// ---------------------------------------------------------------------------
// Kernel 1: precompute.
//   blocks [0, PBLK):        P16[v]    = fp16(u2e[v])        @ W1[0:64]
//   blocks [PBLK, PBLK+NBLK): A1Bn16[b] = fp16(u2e[nodes[b]]) @ a1W[64:128]
// ---------------------------------------------------------------------------
__global__ void __launch_bounds__(256) k_pre(const float* __restrict__ u2e,
                                             const int*   __restrict__ nodes)
{
    __shared__ u32 sBF[4096];

    const int tid = threadIdx.x;
    {
        const uint4* src = reinterpret_cast<const uint4*>(g_Wf + 3 * 2048);
        uint4* dst = reinterpret_cast<uint4*>(sBF);
        for (int i = tid; i < 1024; i += 256) dst[i] = src[i];
    }
    __syncthreads();

    const int wid  = tid >> 5;
    const int lane = tid & 31;
    const int g    = lane >> 2;
    const int q2   = (lane & 3) << 1;
    const int slot = (lane & 3) * 8;

    const bool isP = (blockIdx.x < PBLK);
    int r0, r1;                 // output row indices
    const float *M0, *M1;       // source u2e rows

    if (isP) {
        const int wt = blockIdx.x * 8 + wid;
        if (wt >= VTILE) return;
        r0 = wt * 16 + g;  r1 = r0 + 8;
        M0 = u2e + (size_t)r0 * 64;
        M1 = u2e + (size_t)r1 * 64;
    } else {
        const int wt = (blockIdx.x - PBLK) * 8 + wid;
        if (wt >= BTILE) return;
        r0 = wt * 16 + g;  r1 = r0 + 8;
        M0 = u2e + (size_t)__ldg(&nodes[r0]) * 64;
        M1 = u2e + (size_t)__ldg(&nodes[r1]) * 64;
    }

    u32 ah[16];
    #pragma unroll
    for (int rr = 0; rr < 2; rr++) {
        const float* Mr = rr ? M1 : M0;
        #pragma unroll
        for (int kt = 0; kt < 4; kt++) {
            const int c0 = kt*16 + q2;
            const float2 pa = *reinterpret_cast<const float2*>(Mr + c0);
            const float2 pb = *reinterpret_cast<const float2*>(Mr + c0 + 8);
            ah[kt*4 + rr]     = pack_h2(pa.x, pa.y);
            ah[kt*4 + 2 + rr] = pack_h2(pb.x, pb.y);
        }
    }

    float D[32];
    gemm64_1t(D, ah, isP ? sBF : (sBF + 2048), lane);

    u32 p01[8], p23[8];
    #pragma unroll
    for (int nt = 0; nt < 8; nt++) {
        p01[nt] = pack_h2(D[nt*4+0], D[nt*4+1]);
        p23[nt] = pack_h2(D[nt*4+2], D[nt*4+3]);
    }
    u32* T = isP ? g_P16 : g_A1Bn16;
    uint4* o0 = reinterpret_cast<uint4*>(&T[(size_t)r0 * 32 + slot]);
    uint4* o1 = reinterpret_cast<uint4*>(&T[(size_t)r1 * 32 + slot]);
    o0[0] = make_uint4(p01[0], p01[1], p01[2], p01[3]);
    o0[1] = make_uint4(p01[4], p01[5], p01[6], p01[7]);
    o1[0] = make_uint4(p23[0], p23[1], p23[2], p23[3]);
    o1[1] = make_uint4(p23[4], p23[5], p23[6], p23[7]);
}

// ---------------------------------------------------------------------------
// Main kernel: layer 1 via MMA (labels+bias folded), layers 2-4 via MMA.
// fp16 slot-layout gathers. Dead-row (k >= len) o/score stores skipped.
// ---------------------------------------------------------------------------
#define DSM_U32  (6144 + 512 + 4*64)   // 6912 u32 = 27648 B
#define DSM_BYTES (DSM_U32 * 4)

__global__ void __launch_bounds__(128, 2) k_main(
    const int*   __restrict__ nidx,
    const int*   __restrict__ nlen,
    const float* __restrict__ labels,
    const float* __restrict__ w2b,
    const float* __restrict__ a1b,
    const float* __restrict__ a2b,
    const float* __restrict__ a3W,
    const float* __restrict__ a3b)
{
    extern __shared__ u32 dsm[];
    u32*   sBF  = dsm;                       // 6144 u32: L=0,1,2
    u32*   sBF1 = dsm + 6144;                // 512 u32: W1X kt0
    float* sB2  = (float*)(dsm + 6656);      // 64
    float* sBa1 = sB2 + 64;
    float* sBa2 = sBa1 + 64;
    float* sA3  = sBa2 + 64;

    const int tid = threadIdx.x;
    {
        const uint4* src = reinterpret_cast<const uint4*>(g_Wf);
        uint4* dst = reinterpret_cast<uint4*>(sBF);
        for (int i = tid; i < 1536; i += 128) dst[i] = src[i];
        const uint4* src1 = reinterpret_cast<const uint4*>(g_Wf + 5 * 2048);
        uint4* dst1 = reinterpret_cast<uint4*>(sBF1);
        if (tid < 128) dst1[tid] = src1[tid];
        if (tid < 64) {
            sB2 [tid] = w2b[tid];
            sBa1[tid] = a1b[tid];
            sBa2[tid] = a2b[tid];
            sA3 [tid] = a3W[tid];
        }
    }
    __syncthreads();

    const float a3b0 = a3b[0];
    const int wid  = tid >> 5;             // 0..3
    const int lane = tid & 31;
    const int g    = lane >> 2;            // 0..7
    const int q2   = (lane & 3) << 1;      // 0,2,4,6
    const int l4x2 = (lane & 3) * 2;       // uint4 index within slot row
    const u32 onehot = (q2 == 0) ? pack_h2(1.f, 0.f) : 0u;

    for (int t = blockIdx.x; t < NTILE; t += gridDim.x) {
        const int pb = t * 128 + wid * 32 + g;   // rows pb, pb+8, pb+16, pb+24

        // per-row node slot / neighbor-index / live flag
        int  bidx[4];
        bool live[4];
        #pragma unroll
        for (int rr = 0; rr < 4; rr++) {
            const int p = pb + rr * 8;
            bidx[rr] = p / K_N;
            const int k = p - bidx[rr] * K_N;
            live[rr] = (k < __ldg(&nlen[bidx[rr]]));
        }

        u32 ahA[16], ahB[16];
        float D[64];

        // ====== LAYER 1 via MMA: D = [labels,1,0..] @ [W1L; b1; 0] ======
        {
            u32 lF[8];
            const uint4* Pr[4];
            #pragma unroll
            for (int rr = 0; rr < 4; rr++) {
                const int p = pb + rr * 8;
                const float2 l2 = *reinterpret_cast<const float2*>(labels + (size_t)p * 8 + q2);
                u32* lf = (rr < 2) ? lF : lF + 4;
                const int sl = rr & 1;
                lf[0 + sl] = pack_h2(l2.x, l2.y);
                lf[2 + sl] = onehot;
                Pr[rr] = reinterpret_cast<const uint4*>(g_P16 + (size_t)__ldg(&nidx[p]) * 32);
            }

            #pragma unroll
            for (int nt = 0; nt < 8; nt++) {
                float d0=0.f,d1=0.f,d2=0.f,d3=0.f,d4=0.f,d5=0.f,d6=0.f,d7=0.f;
                const uint2 b = *reinterpret_cast<const uint2*>(sBF1 + nt*64 + lane*2);
                mma16816(d0,d1,d2,d3, lF[0],lF[1],lF[2],lF[3], b.x,b.y);
                mma16816(d4,d5,d6,d7, lF[4],lF[5],lF[6],lF[7], b.x,b.y);
                D[nt*8+0]=d0; D[nt*8+1]=d1; D[nt*8+2]=d2; D[nt*8+3]=d3;
                D[nt*8+4]=d4; D[nt*8+5]=d5; D[nt*8+6]=d6; D[nt*8+7]=d7;
            }

            // h = relu(D + P16[ni]) -> A fragments (hi only)
            #pragma unroll
            for (int rr = 0; rr < 4; rr++) {
                const uint4 pa = Pr[rr][l4x2];
                const uint4 pbq = Pr[rr][l4x2 + 1];
                u32* ah = (rr < 2) ? ahA : ahB;
                const int sl = rr & 1;
                const int hb = (rr >> 1) * 4 + sl * 2;
                const u32 pk[8] = { pa.x, pa.y, pa.z, pa.w, pbq.x, pbq.y, pbq.z, pbq.w };
                #pragma unroll
                for (int nt = 0; nt < 8; nt++) {
                    const float2 pv = h2f(pk[nt]);
                    const float v0 = fmaxf(D[nt*8 + hb + 0] + pv.x, 0.f);
                    const float v1 = fmaxf(D[nt*8 + hb + 1] + pv.y, 0.f);
                    ah[(nt >> 1)*4 + (nt & 1)*2 + sl] = pack_h2(v0, v1);
                }
            }
        }

        // ================= LAYER 2: o = relu(h @ W2 + b2) =================
        gemm64x2_1t(D, ahA, ahB, sBF, lane);
        {
            u32 p01[8], p23[8], q01[8], q23[8];
            #pragma unroll
            for (int nt = 0; nt < 8; nt++) {
                const int c0 = nt * 8 + q2;
                const int kt = nt >> 1, hf = nt & 1;
                const float b0 = sB2[c0], b1 = sB2[c0 + 1];
                p01[nt] = pack_h2(fmaxf(D[nt*8+0] + b0, 0.f), fmaxf(D[nt*8+1] + b1, 0.f));
                p23[nt] = pack_h2(fmaxf(D[nt*8+2] + b0, 0.f), fmaxf(D[nt*8+3] + b1, 0.f));
                q01[nt] = pack_h2(fmaxf(D[nt*8+4] + b0, 0.f), fmaxf(D[nt*8+5] + b1, 0.f));
                q23[nt] = pack_h2(fmaxf(D[nt*8+6] + b0, 0.f), fmaxf(D[nt*8+7] + b1, 0.f));
                ahA[kt*4 + hf*2 + 0] = p01[nt];
                ahA[kt*4 + hf*2 + 1] = p23[nt];
                ahB[kt*4 + hf*2 + 0] = q01[nt];
                ahB[kt*4 + hf*2 + 1] = q23[nt];
            }
            // stores only for live rows (k < len) — dead rows never read
            const int slot = (lane & 3) * 8;
            if (live[0]) {
                uint4* r = reinterpret_cast<uint4*>(&g_O16[(size_t)(pb     ) * 32 + slot]);
                r[0] = make_uint4(p01[0], p01[1], p01[2], p01[3]);
                r[1] = make_uint4(p01[4], p01[5], p01[6], p01[7]);
            }
            if (live[1]) {
                uint4* r = reinterpret_cast<uint4*>(&g_O16[(size_t)(pb +  8) * 32 + slot]);
                r[0] = make_uint4(p23[0], p23[1], p23[2], p23[3]);
                r[1] = make_uint4(p23[4], p23[5], p23[6], p23[7]);
            }
            if (live[2]) {
                uint4* r = reinterpret_cast<uint4*>(&g_O16[(size_t)(pb + 16) * 32 + slot]);
                r[0] = make_uint4(q01[0], q01[1], q01[2], q01[3]);
                r[1] = make_uint4(q01[4], q01[5], q01[6], q01[7]);
            }
            if (live[3]) {
                uint4* r = reinterpret_cast<uint4*>(&g_O16[(size_t)(pb + 24) * 32 + slot]);
                r[0] = make_uint4(q23[0], q23[1], q23[2], q23[3]);
                r[1] = make_uint4(q23[4], q23[5], q23[6], q23[7]);
            }
        }

        // ===== LAYER 3: a = relu(o @ A1a + A1Bn[b] + b) (scores only) =====
        const uint4* G[4];
        #pragma unroll
        for (int rr = 0; rr < 4; rr++)
            G[rr] = reinterpret_cast<const uint4*>(g_A1Bn16 + (size_t)bidx[rr] * 32);

        gemm64x2_1t(D, ahA, ahB, sBF + 2048, lane);
        #pragma unroll
        for (int rr = 0; rr < 4; rr++) {
            const uint4 ga = G[rr][l4x2];
            const uint4 gb = G[rr][l4x2 + 1];
            u32* ah = (rr < 2) ? ahA : ahB;
            const int sl = rr & 1;
            const int hb = (rr >> 1) * 4 + sl * 2;
            const u32 gk[8] = { ga.x, ga.y, ga.z, ga.w, gb.x, gb.y, gb.z, gb.w };
            #pragma unroll
            for (int nt = 0; nt < 8; nt++) {
                const float2 gv = h2f(gk[nt]);
                const int c0 = nt * 8 + q2;
                const float v0 = fmaxf(D[nt*8 + hb + 0] + sBa1[c0]     + gv.x, 0.f);
                const float v1 = fmaxf(D[nt*8 + hb + 1] + sBa1[c0 + 1] + gv.y, 0.f);
                ah[(nt >> 1)*4 + (nt & 1)*2 + sl] = pack_h2(v0, v1);
            }
        }

        // ========= LAYER 4: a2 = relu(a @ A2 + b); score = a2 . a3 ========
        gemm64x2_1t(D, ahA, ahB, sBF + 4096, lane);
        float s[4] = {0.f, 0.f, 0.f, 0.f};
        #pragma unroll
        for (int nt = 0; nt < 8; nt++) {
            const int c0 = nt * 8 + q2;
            const float b0 = sBa2[c0], b1 = sBa2[c0 + 1];
            const float w0 = sA3[c0],  w1 = sA3[c0 + 1];
            #pragma unroll
            for (int half = 0; half < 2; half++) {
                const float v0 = fmaxf(D[nt*8 + half*4 + 0] + b0, 0.f);
                const float v1 = fmaxf(D[nt*8 + half*4 + 1] + b1, 0.f);
                const float v2 = fmaxf(D[nt*8 + half*4 + 2] + b0, 0.f);
                const float v3 = fmaxf(D[nt*8 + half*4 + 3] + b1, 0.f);
                s[half*2]     = fmaf(v0, w0, fmaf(v1, w1, s[half*2]));
                s[half*2 + 1] = fmaf(v2, w0, fmaf(v3, w1, s[half*2 + 1]));
            }
        }
        #pragma unroll
        for (int rr = 0; rr < 4; rr++) {
            float sv = s[rr];
            sv += __shfl_xor_sync(0xffffffffu, sv, 1);
            sv += __shfl_xor_sync(0xffffffffu, sv, 2);
            if ((lane & 3) == 0 && live[rr]) g_S[pb + rr * 8] = sv + a3b0;
        }
    }
}

// ---------------------------------------------------------------------------
// Kernel 3: masked softmax + aggregate (R14/R16 proven loop). Column map:
// slot=lane ↔ columns (lane&7)*8 + (lane>>3)*2 + {0,1}.
// ---------------------------------------------------------------------------
__global__ void __launch_bounds__(256) k_agg(const int*   __restrict__ nodes,
                                             const int*   __restrict__ nlen,
                                             const float* __restrict__ u2e,
                                             float*       __restrict__ out)
{
    const int wid  = (blockIdx.x * 256 + threadIdx.x) >> 5;
    const int lane = threadIdx.x & 31;
    if (wid >= B_N) return;
    const int b   = wid;
    const int len = nlen[b];

    if (len <= 0) {
        const int node = nodes[b];
        const float2* src = reinterpret_cast<const float2*>(u2e + (size_t)node * 64);
        reinterpret_cast<float2*>(out + (size_t)b * 64)[lane] = src[lane];
        return;
    }

    const float* Sb = g_S + (size_t)b * K_N;
    float s0 = (lane      < len) ? Sb[lane]      : -3.0e38f;
    float s1 = (lane + 32 < len) ? Sb[lane + 32] : -3.0e38f;

    float m = fmaxf(s0, s1);
    #pragma unroll
    for (int o = 16; o > 0; o >>= 1) m = fmaxf(m, __shfl_xor_sync(0xffffffffu, m, o));

    const float e0 = (lane      < len) ? expf(s0 - m) : 0.f;
    const float e1 = (lane + 32 < len) ? expf(s1 - m) : 0.f;

    float ss = e0 + e1;
    #pragma unroll
    for (int o = 16; o > 0; o >>= 1) ss += __shfl_xor_sync(0xffffffffu, ss, o);

    const float inv = 1.f / ss;
    const float w0 = e0 * inv;
    const float w1 = e1 * inv;

    float2 agg = make_float2(0.f, 0.f);
    const u32* Ob = g_O16 + (size_t)b * K_N * 32;
    for (int k = 0; k < len; k++) {
        const float ak = (k < 32) ? __shfl_sync(0xffffffffu, w0, k)
                                  : __shfl_sync(0xffffffffu, w1, k - 32);
        const u32 ov = Ob[k * 32 + lane];
        const float2 of = h2f(ov);
        agg.x = fmaf(ak, of.x, agg.x);
        agg.y = fmaf(ak, of.y, agg.y);
    }
    const int col = (lane & 7) * 8 + (lane >> 3) * 2;
    *reinterpret_cast<float2*>(out + (size_t)b * 64 + col) = agg;
}

// ---------------------------------------------------------------------------
// kernel_launch
// ---------------------------------------------------------------------------
extern "C" void kernel_launch(void* const* d_in, const int* in_sizes, int n_in,
                              void* d_out, int out_size)
{
    const int*   nodes  = (const int*)  d_in[0];
    const int*   nidx   = (const int*)  d_in[1];
    const int*   nlen   = (const int*)  d_in[2];
    const float* labels = (const float*)d_in[3];
    const float* u2e    = (const float*)d_in[4];
    const float* w1W    = (const float*)d_in[5];
    const float* w1b    = (const float*)d_in[6];
    const float* w2W    = (const float*)d_in[7];
    const float* w2b    = (const float*)d_in[8];
    const float* a1W    = (const float*)d_in[9];
    const float* a1b    = (const float*)d_in[10];
    const float* a2W    = (const float*)d_in[11];
    const float* a2b    = (const float*)d_in[12];
    const float* a3W    = (const float*)d_in[13];
    const float* a3b    = (const float*)d_in[14];
    float* out = (float*)d_out;

    cudaFuncSetAttribute(k_main, cudaFuncAttributeMaxDynamicSharedMemorySize, DSM_BYTES);

    k_wfrag<<<21, 256>>>(w2W, a1W, a2W, w1W, w1b);
    k_pre  <<<PBLK + NBLK, 256>>>(u2e, nodes);
    k_main <<<296, 128, DSM_BYTES>>>(nidx, nlen, labels,
                                     w2b, a1b, a2b, a3W, a3b);
    k_agg  <<<(B_N * 32 + 255) / 256, 256>>>(nodes, nlen, u2e, out);
}